// round 16
// baseline (speedup 1.0000x reference)
#include <cuda_runtime.h>
#include <cuda_bf16.h>
#include <cstdint>

typedef unsigned long long u64;
typedef unsigned int u32;

// Problem constants
#define BB 32
#define TT 512
#define II 512
#define HH 512
#define G4H 2048
#define EE 4
#define OUTD 512
#define NPAIR 64
#define NCHAIN 128
#define LSTM_BLOCKS 128

// recurrence smem layout (bytes)
#define WF_U64   16384
#define HSTR     516
#define HS_F32   (32 * HSTR)
#define RSTR     17
#define RED_HALF (8 * 32 * RSTR)                 // one k-half buffer (f32)
#define RED_F32  (2 * RED_HALF)                  // 8704 f32 = 34,816 B
#define SMEM_BYTES (WF_U64 * 8 + HS_F32 * 4 + RED_F32 * 4)   // 231,936 B

// xp mma smem
#define XSTR 18
#define XP_SMEM_BYTES (2 * 2 * 128 * XSTR * 4)   // 73,728 B

// ---------------- device scratch ----------------------------------------------
// g_xp inner layout: [chain][t][j*4 + gate]  (gate-interleaved for LDG.128 tail)
__device__ __align__(16) float g_xp[(size_t)NCHAIN * TT * G4H];       // 512 MB
__device__ __align__(16) float g_hout[(size_t)NPAIR * TT * 2 * HH];   // 128 MB
__device__ __align__(16) float g_hbuf[2][NCHAIN * HH];
__device__ __align__(16) float g_router_h[BB * II];
__device__ int   g_pair_b[NPAIR];
__device__ int   g_pair_e[NPAIR];
__device__ int   g_off[EE];
__device__ int   g_cnt[EE];
__device__ int   g_bpair[BB * 2];
__device__ float g_bw[BB * 2];
__device__ float g_lb;
__device__ int   g_gbar[8];

// ---------------- helpers ------------------------------------------------------
__device__ __forceinline__ u64 ffma2(u64 a, u64 b, u64 c) {
    u64 d;
    asm("fma.rn.f32x2 %0, %1, %2, %3;" : "=l"(d) : "l"(a), "l"(b), "l"(c));
    return d;
}
__device__ __forceinline__ float f2sum(u64 v) {
    float lo, hi;
    asm("mov.b64 {%0,%1}, %2;" : "=f"(lo), "=f"(hi) : "l"(v));
    return lo + hi;
}
__device__ __forceinline__ u64 pack2(float lo, float hi) {
    u64 v;
    asm("mov.b64 %0, {%1,%2};" : "=l"(v) : "f"(lo), "f"(hi));
    return v;
}
__device__ __forceinline__ float sigmoid_fast(float x) {
    return 0.5f * __tanhf(0.5f * x) + 0.5f;
}
__device__ __forceinline__ int ld_acq(const int* p) {
    int v;
    asm volatile("ld.acquire.gpu.b32 %0, [%1];" : "=r"(v) : "l"(p));
    return v;
}
__device__ __forceinline__ void red_release_add(int* p, int v) {
    asm volatile("red.release.gpu.global.add.s32 [%0], %1;" :: "l"(p), "r"(v) : "memory");
}
__device__ __forceinline__ u32 f2tf(float f) {
    u32 r;
    asm("cvt.rna.tf32.f32 %0, %1;" : "=r"(r) : "f"(f));
    return r;
}
__device__ __forceinline__ void mma_tf32(float& d0, float& d1, float& d2, float& d3,
                                         u32 a0, u32 a1, u32 a2, u32 a3,
                                         u32 b0, u32 b1) {
    asm("mma.sync.aligned.m16n8k8.row.col.f32.tf32.tf32.f32 "
        "{%0,%1,%2,%3}, {%4,%5,%6,%7}, {%8,%9}, {%0,%1,%2,%3};"
        : "+f"(d0), "+f"(d1), "+f"(d2), "+f"(d3)
        : "r"(a0), "r"(a1), "r"(a2), "r"(a3), "r"(b0), "r"(b1));
}

// ---- launch 1: fused init + mean + router layer 1 ------------------------------
__global__ __launch_bounds__(512) void init_mean_r1_kernel(
    const float* __restrict__ x, const float* __restrict__ rW1,
    const float* __restrict__ rb1)
{
    int bid = blockIdx.x;
    int tid = threadIdx.x;
    if (bid < BB) {
        __shared__ float rin[II];
        const float* xb = x + (size_t)bid * TT * II + tid;
        float s = 0.f;
        for (int t = 0; t < TT; t++) s += xb[(size_t)t * II];
        rin[tid] = s * (1.0f / (float)TT);
        __syncthreads();
        int n = tid;
        u64 acc2 = 0ull;
        const float* w = rW1 + (size_t)n * II;
        for (int k = 0; k < II; k += 4) {
            float4 wv = *(const float4*)(w + k);
            float4 rv = *(const float4*)&rin[k];
            acc2 = ffma2(pack2(rv.x, rv.y), pack2(wv.x, wv.y), acc2);
            acc2 = ffma2(pack2(rv.z, rv.w), pack2(wv.z, wv.w), acc2);
        }
        float v = f2sum(acc2) + rb1[n];
        float sg = 1.f / (1.f + expf(-v));
        g_router_h[bid * II + n] = v * sg;
    } else {
        int idx = (bid - BB) * 512 + tid;
        g_hbuf[0][idx] = 0.f;
        g_hbuf[0][idx + 32768] = 0.f;
        g_hbuf[1][idx] = 0.f;
        g_hbuf[1][idx + 32768] = 0.f;
        if (bid == BB && tid < 8) g_gbar[tid] = 0;
    }
}

// ---- launch 2: router layer 2 + softmax + top-2 + pair lists -------------------
__global__ __launch_bounds__(128, 1) void router2_kernel(
    const float* __restrict__ rW2, const float* __restrict__ rb2)
{
    __shared__ float logits[BB][EE];
    __shared__ float probs[BB][EE];
    __shared__ float gate[BB][EE];
    int tid = threadIdx.x;
    {
        int b = tid >> 2, e = tid & 3;
        float s = rb2[e];
        const float* w = rW2 + (size_t)e * II;
        const float* h = g_router_h + (size_t)b * II;
        for (int k = 0; k < II; k++) s += h[k] * w[k];
        logits[b][e] = s;
    }
    __syncthreads();
    if (tid < BB) {
        int b = tid;
        float m = logits[b][0];
        for (int e = 1; e < EE; e++) m = fmaxf(m, logits[b][e]);
        float pr[EE], sum = 0.f;
        for (int e = 0; e < EE; e++) { pr[e] = expf(logits[b][e] - m); sum += pr[e]; }
        for (int e = 0; e < EE; e++) { pr[e] /= sum; probs[b][e] = pr[e]; gate[b][e] = 0.f; }
        int i1 = 0;
        for (int e = 1; e < EE; e++) if (pr[e] > pr[i1]) i1 = e;
        int i2 = -1;
        for (int e = 0; e < EE; e++) {
            if (e == i1) continue;
            if (i2 < 0 || pr[e] > pr[i2]) i2 = e;
        }
        float ws = pr[i1] + pr[i2];
        gate[b][i1] = pr[i1] / ws;
        gate[b][i2] = pr[i2] / ws;
    }
    __syncthreads();
    if (tid == 0) {
        float lb = 0.f;
        for (int e = 0; e < EE; e++) {
            float u = 0.f;
            for (int b = 0; b < BB; b++) u += probs[b][e];
            u *= (1.f / (float)BB);
            float d = u - 1.0f / (float)EE;
            lb += d * d;
        }
        g_lb = 0.01f * (lb / (float)EE);
        int P = 0;
        int slotc[BB];
        for (int b = 0; b < BB; b++) slotc[b] = 0;
        for (int e = 0; e < EE; e++) {
            g_off[e] = P;
            for (int b = 0; b < BB; b++) {
                if (gate[b][e] > 0.f) {
                    g_pair_b[P] = b;
                    g_pair_e[P] = e;
                    g_bpair[b * 2 + slotc[b]] = P;
                    g_bw[b * 2 + slotc[b]] = gate[b][e];
                    slotc[b]++;
                    P++;
                }
            }
            g_cnt[e] = P - g_off[e];
        }
    }
}

// ---------------- xp GEMM on tensor pipe (tf32 m16n8k8) ------------------------
// Output layout: C[t][j*4 + gate] where original col c = gate*512 + j.
__global__ __launch_bounds__(256, 2) void xp_gemm_mma_kernel(
    const float* __restrict__ x, const float* __restrict__ Wih,
    const float* __restrict__ bih, const float* __restrict__ bhh)
{
    extern __shared__ u32 xsm[];
    u32* As = xsm;
    u32* Bs = xsm + 2 * 128 * XSTR;

    int z = blockIdx.z;
    int p = z >> 1, d = z & 1;
    int b = g_pair_b[p];
    int e = g_pair_e[p];
    int ed = e * 2 + d;
    const float* A  = x + (size_t)b * TT * II;
    const float* Bw = Wih + (size_t)ed * G4H * II;
    const float* b1 = bih + (size_t)ed * G4H;
    const float* b2 = bhh + (size_t)ed * G4H;
    float* C = g_xp + (size_t)z * TT * G4H;
    int m0 = blockIdx.y * 128, n0 = blockIdx.x * 128;

    int tid = threadIdx.x;
    int w = tid >> 5, lane = tid & 31;
    int wm = w >> 2, wn = w & 3;
    int lg = lane >> 2, lt = lane & 3;

    float acc[4][4][4];
#pragma unroll
    for (int mt = 0; mt < 4; mt++)
#pragma unroll
        for (int nt = 0; nt < 4; nt++)
#pragma unroll
            for (int q = 0; q < 4; q++) acc[mt][nt][q] = 0.f;

    int srow[2], skv[2], spb[2];
#pragma unroll
    for (int it = 0; it < 2; it++) {
        int idx = tid + it * 256;
        srow[it] = idx >> 2;
        skv[it] = (idx & 3) * 4;
        spb[it] = 8 * (skv[it] >> 3) + ((skv[it] >> 2) & 1);
    }

    float4 pa[2], pbv[2];
#pragma unroll
    for (int it = 0; it < 2; it++) {
        pa[it]  = *(const float4*)(A  + (size_t)(m0 + srow[it]) * II + skv[it]);
        pbv[it] = *(const float4*)(Bw + (size_t)(n0 + srow[it]) * II + skv[it]);
    }

    for (int kt = 0; kt < 32; kt++) {
        int bsel = kt & 1;
        u32* Ab = As + bsel * (128 * XSTR);
        u32* Bb = Bs + bsel * (128 * XSTR);
#pragma unroll
        for (int it = 0; it < 2; it++) {
            int abase = srow[it] * XSTR + spb[it];
            Ab[abase + 0] = f2tf(pa[it].x);
            Ab[abase + 2] = f2tf(pa[it].y);
            Ab[abase + 4] = f2tf(pa[it].z);
            Ab[abase + 6] = f2tf(pa[it].w);
            Bb[abase + 0] = f2tf(pbv[it].x);
            Bb[abase + 2] = f2tf(pbv[it].y);
            Bb[abase + 4] = f2tf(pbv[it].z);
            Bb[abase + 6] = f2tf(pbv[it].w);
        }
        __syncthreads();
        if (kt < 31) {
            int k0n = (kt + 1) * 16;
#pragma unroll
            for (int it = 0; it < 2; it++) {
                pa[it]  = *(const float4*)(A  + (size_t)(m0 + srow[it]) * II + k0n + skv[it]);
                pbv[it] = *(const float4*)(Bw + (size_t)(n0 + srow[it]) * II + k0n + skv[it]);
            }
        }
#pragma unroll
        for (int h = 0; h < 2; h++) {
            u32 a0[4], a1[4], a2[4], a3[4];
#pragma unroll
            for (int mt = 0; mt < 4; mt++) {
                int r = wm * 64 + mt * 16 + lg;
                u64 v  = *(const u64*)&Ab[r * XSTR + h * 8 + 2 * lt];
                u64 v2 = *(const u64*)&Ab[(r + 8) * XSTR + h * 8 + 2 * lt];
                a0[mt] = (u32)v;  a2[mt] = (u32)(v >> 32);
                a1[mt] = (u32)v2; a3[mt] = (u32)(v2 >> 32);
            }
            u32 bf0[4], bf1[4];
#pragma unroll
            for (int nt = 0; nt < 4; nt++) {
                int rn = wn * 32 + nt * 8 + lg;
                u64 v = *(const u64*)&Bb[rn * XSTR + h * 8 + 2 * lt];
                bf0[nt] = (u32)v; bf1[nt] = (u32)(v >> 32);
            }
#pragma unroll
            for (int mt = 0; mt < 4; mt++)
#pragma unroll
                for (int nt = 0; nt < 4; nt++)
                    mma_tf32(acc[mt][nt][0], acc[mt][nt][1], acc[mt][nt][2], acc[mt][nt][3],
                             a0[mt], a1[mt], a2[mt], a3[mt], bf0[nt], bf1[nt]);
        }
    }

    // epilogue: permuted store  c = gate*512 + j  ->  offset j*4 + gate
#pragma unroll
    for (int mt = 0; mt < 4; mt++) {
        int r0 = m0 + wm * 64 + mt * 16 + lg;
#pragma unroll
        for (int nt = 0; nt < 4; nt++) {
            int c0 = n0 + wn * 32 + nt * 8 + 2 * lt;     // even, c0+1 same gate
            int gate = c0 >> 9;
            int j = c0 & 511;
            float bv0 = b1[c0] + b2[c0];
            float bv1 = b1[c0 + 1] + b2[c0 + 1];
            size_t o0 = (size_t)r0 * G4H + (size_t)j * 4 + gate;
            size_t o1 = (size_t)(r0 + 8) * G4H + (size_t)j * 4 + gate;
            C[o0]     = acc[mt][nt][0] + bv0;
            C[o0 + 4] = acc[mt][nt][1] + bv1;
            C[o1]     = acc[mt][nt][2] + bv0;
            C[o1 + 4] = acc[mt][nt][3] + bv1;
        }
    }
}

// ---------- out-proj: exact fp32 FFMA2, fused gate-combine + lb write ----------
#define TMm 128
#define TNn 128
#define TKk 16

__global__ __launch_bounds__(256, 1) void out_gemm_fused_kernel(
    const float* __restrict__ Wout, const float* __restrict__ bout,
    float* __restrict__ out, int out_size)
{
    const int K = 2 * HH;
    int m0 = blockIdx.y * TMm, n0 = blockIdx.x * TNn;
    __shared__ float2 As2[2][TKk / 2][TMm + 1];
    __shared__ float2 Bs2[2][TKk / 2][TNn + 1];
    int tid = threadIdx.x;
    int tx = tid & 15;
    int ty = tid >> 4;
    u64 acc2[8][8];
#pragma unroll
    for (int i = 0; i < 8; i++)
#pragma unroll
        for (int j = 0; j < 8; j++) acc2[i][j] = 0ull;

    int arow[2], akv[2];
    int ap0[2], ap1[2];
    float aw0[2], aw1[2];
#pragma unroll
    for (int it = 0; it < 2; it++) {
        int idx = tid + it * 256;
        arow[it] = idx >> 2;
        akv[it]  = (idx & 3) * 4;
        int m = m0 + arow[it];
        int b = m >> 9;
        ap0[it] = g_bpair[b * 2 + 0]; ap1[it] = g_bpair[b * 2 + 1];
        aw0[it] = g_bw[b * 2 + 0];    aw1[it] = g_bw[b * 2 + 1];
    }

    float4 pa[2], pb[2];
#pragma unroll
    for (int it = 0; it < 2; it++) {
        int m = m0 + arow[it];
        int t = m & (TT - 1);
        const float* h0 = g_hout + ((size_t)ap0[it] * TT + t) * (2 * HH) + akv[it];
        const float* h1 = g_hout + ((size_t)ap1[it] * TT + t) * (2 * HH) + akv[it];
        float4 v0 = __ldg((const float4*)h0);
        float4 v1 = __ldg((const float4*)h1);
        pa[it] = make_float4(aw0[it] * v0.x + aw1[it] * v1.x, aw0[it] * v0.y + aw1[it] * v1.y,
                             aw0[it] * v0.z + aw1[it] * v1.z, aw0[it] * v0.w + aw1[it] * v1.w);
        pb[it] = *(const float4*)(Wout + (size_t)(n0 + arow[it]) * K + akv[it]);
    }
    int nk = K / TKk;
    for (int kt = 0; kt < nk; kt++) {
        int bsel = kt & 1;
#pragma unroll
        for (int it = 0; it < 2; it++) {
            int row = arow[it];
            int kv2 = (akv[it] >> 1);
            As2[bsel][kv2][row]     = make_float2(pa[it].x, pa[it].y);
            As2[bsel][kv2 + 1][row] = make_float2(pa[it].z, pa[it].w);
            Bs2[bsel][kv2][row]     = make_float2(pb[it].x, pb[it].y);
            Bs2[bsel][kv2 + 1][row] = make_float2(pb[it].z, pb[it].w);
        }
        __syncthreads();
        if (kt + 1 < nk) {
            int k0n = (kt + 1) * TKk;
#pragma unroll
            for (int it = 0; it < 2; it++) {
                int m = m0 + arow[it];
                int t = m & (TT - 1);
                const float* h0 = g_hout + ((size_t)ap0[it] * TT + t) * (2 * HH) + k0n + akv[it];
                const float* h1 = g_hout + ((size_t)ap1[it] * TT + t) * (2 * HH) + k0n + akv[it];
                float4 v0 = __ldg((const float4*)h0);
                float4 v1 = __ldg((const float4*)h1);
                pa[it] = make_float4(aw0[it] * v0.x + aw1[it] * v1.x, aw0[it] * v0.y + aw1[it] * v1.y,
                                     aw0[it] * v0.z + aw1[it] * v1.z, aw0[it] * v0.w + aw1[it] * v1.w);
                pb[it] = *(const float4*)(Wout + (size_t)(n0 + arow[it]) * K + k0n + akv[it]);
            }
        }
#pragma unroll
        for (int kk2 = 0; kk2 < TKk / 2; kk2++) {
            u64 a2[8], b2[8];
#pragma unroll
            for (int i = 0; i < 8; i++) a2[i] = *(const u64*)&As2[bsel][kk2][ty + 16 * i];
#pragma unroll
            for (int j = 0; j < 8; j++) b2[j] = *(const u64*)&Bs2[bsel][kk2][tx + 16 * j];
#pragma unroll
            for (int i = 0; i < 8; i++)
#pragma unroll
                for (int j = 0; j < 8; j++) acc2[i][j] = ffma2(a2[i], b2[j], acc2[i][j]);
        }
    }
#pragma unroll
    for (int j = 0; j < 8; j++) {
        int n = n0 + tx + 16 * j;
        float bv = bout[n];
#pragma unroll
        for (int i = 0; i < 8; i++) {
            int m = m0 + ty + 16 * i;
            out[(size_t)m * OUTD + n] = f2sum(acc2[i][j]) + bv;
        }
    }
    if (blockIdx.x == 0 && blockIdx.y == 0 && tid == 0)
        out[out_size - 1] = g_lb;
}

// ---- persistent LSTM recurrence: tf32 mma, k-split + nt-skip + 1-sync red ----
__global__ __launch_bounds__(512, 1) void lstm_persist_kernel(const float* __restrict__ Whh) {
    extern __shared__ __align__(16) char smem_dyn[];
    u64* wfrag = (u64*)smem_dyn;
    u32* hs    = (u32*)(smem_dyn + WF_U64 * 8);
    float* red = (float*)(smem_dyn + WF_U64 * 8 + HS_F32 * 4);   // [kh][og*32+lane][17]

    int bid = blockIdx.x;
    int g = bid >> 4;
    int ct = bid & 15;
    int e = g >> 1, d = g & 1;
    int cnt = g_cnt[e];
    int off = g_off[e];
    int j0 = ct * 32;
    if (cnt == 0) return;
    int rows_used = (cnt + 7) & ~7;          // block-uniform, <= 32
    int hfill_iters = rows_used >> 2;        // rows_used*128/512

    int tid = threadIdx.x;
    int w = tid >> 5, lane = tid & 31;
    int kh = w & 1, og = w >> 1;

    const float* W = Whh + (size_t)g * G4H * HH;

    for (int it = 0; it < 32; it++) {
        int id = tid + it * 512;
        int ln = id & 31;
        int kt = (id >> 5) & 63;
        int ogp = id >> 11;
        int gatep = ogp & 3, chp = ogp >> 2;
        int m0 = ln >> 2;
        int k = kt * 8 + (ln & 3);
        int ra = gatep * HH + j0 + chp * 16 + m0;
        float w00 = W[(size_t)ra * HH + k];
        float w10 = W[(size_t)(ra + 8) * HH + k];
        float w01 = W[(size_t)ra * HH + k + 4];
        float w11 = W[(size_t)(ra + 8) * HH + k + 4];
        u32 lo = ((u32)__bfloat16_as_ushort(__float2bfloat16_rn(w00))) |
                 (((u32)__bfloat16_as_ushort(__float2bfloat16_rn(w10))) << 16);
        u32 hi = ((u32)__bfloat16_as_ushort(__float2bfloat16_rn(w01))) |
                 (((u32)__bfloat16_as_ushort(__float2bfloat16_rn(w11))) << 16);
        wfrag[id] = ((u64)hi << 32) | lo;
    }

    int colc[2], rowc[2], chainc[2], lslot[2], iidx[2], ogb[2];
    float c_reg[2];
#pragma unroll
    for (int u = 0; u < 2; u++) {
        int cid = tid * 2 + u;
        colc[u] = cid >> 5;
        rowc[u] = cid & 31;
        chainc[u] = (off + rowc[u]) * 2 + d;
        int m = colc[u] & 15;
        int nt = rowc[u] >> 3;
        lslot[u] = (m & 7) * 4 + ((rowc[u] & 7) >> 1);
        iidx[u] = nt * 4 + (m >> 3) * 2 + (rowc[u] & 1);
        ogb[u] = (colc[u] >> 4) << 2;
        c_reg[u] = 0.f;
    }
    int jcell[2] = { j0 + colc[0], j0 + colc[1] };

    int* bar = &g_gbar[g];
    const u64* wfw = wfrag + (size_t)og * 2048 + (size_t)kh * 32 * 32;
    float* myred = red + kh * RED_HALF + (og * 32 + lane) * RSTR;

    __syncthreads();

    for (int s = 0; s < TT; s++) {
        int rb = s & 1;
        int t = d ? (TT - 1 - s) : s;
        const float* hread = g_hbuf[rb];
        float* hwrite = g_hbuf[rb ^ 1];

        // xp prefetch: 1 LDG.128 per cell (gates interleaved)
        float xq[2][4];
#pragma unroll
        for (int u = 0; u < 2; u++) {
            xq[u][0] = xq[u][1] = xq[u][2] = xq[u][3] = 0.f;
            if (rowc[u] < cnt) {
                float4 xv = __ldg((const float4*)(g_xp +
                    ((size_t)chainc[u] * TT + t) * G4H + (size_t)jcell[u] * 4));
                xq[u][0] = xv.x; xq[u][1] = xv.y; xq[u][2] = xv.z; xq[u][3] = xv.w;
            }
        }

        // h fill: rows_used rows x 128 float4 over 512 threads
        for (int it = 0; it < hfill_iters; it++) {
            int idx = tid + it * 512;
            int row = idx >> 7;
            int f4 = idx & 127;
            float4 v = make_float4(0.f, 0.f, 0.f, 0.f);
            if (row < cnt)
                v = __ldcg((const float4*)(hread + (size_t)((off + row) * 2 + d) * HH + f4 * 4));
            uint4 tv;
            tv.x = f2tf(v.x); tv.y = f2tf(v.y); tv.z = f2tf(v.z); tv.w = f2tf(v.w);
            *(uint4*)&hs[row * HSTR + f4 * 4] = tv;
        }
        __syncthreads();

        float acc[16];
#pragma unroll
        for (int i = 0; i < 16; i++) acc[i] = 0.f;

        int kb = kh * 256;
        int brow = lane >> 2;
        int bk = lane & 3;
#pragma unroll 8
        for (int ktl = 0; ktl < 32; ktl++) {
            u64 wv = wfw[ktl * 32 + lane];
            u32 lo = (u32)wv, hi = (u32)(wv >> 32);
            u32 a0 = lo << 16;
            u32 a1 = lo & 0xFFFF0000u;
            u32 a2 = hi << 16;
            u32 a3 = hi & 0xFFFF0000u;
            int k0 = kb + ktl * 8;
#pragma unroll
            for (int nt = 0; nt < 4; nt++) {
                if (nt * 8 < cnt) {
                    u32 b0 = hs[(nt * 8 + brow) * HSTR + k0 + bk];
                    u32 b1 = hs[(nt * 8 + brow) * HSTR + k0 + bk + 4];
                    mma_tf32(acc[nt * 4 + 0], acc[nt * 4 + 1], acc[nt * 4 + 2], acc[nt * 4 + 3],
                             a0, a1, a2, a3, b0, b1);
                }
            }
        }

        // both k-halves export; single sync; tail adds
#pragma unroll
        for (int i = 0; i < 16; i++) myred[i] = acc[i];
        __syncthreads();

#pragma unroll
        for (int u = 0; u < 2; u++) {
            if (rowc[u] < cnt) {
                int i0 = ((ogb[u] + 0) * 32 + lslot[u]) * RSTR + iidx[u];
                int i1 = ((ogb[u] + 1) * 32 + lslot[u]) * RSTR + iidx[u];
                int i2 = ((ogb[u] + 2) * 32 + lslot[u]) * RSTR + iidx[u];
                int i3 = ((ogb[u] + 3) * 32 + lslot[u]) * RSTR + iidx[u];
                float gi = xq[u][0] + (red[i0] + red[RED_HALF + i0]);
                float gf = xq[u][1] + (red[i1] + red[RED_HALF + i1]);
                float gg = xq[u][2] + (red[i2] + red[RED_HALF + i2]);
                float go = xq[u][3] + (red[i3] + red[RED_HALF + i3]);
                float iv = sigmoid_fast(gi);
                float fv = sigmoid_fast(gf);
                float gv = __tanhf(gg);
                float ov = sigmoid_fast(go);
                float cvv = fv * c_reg[u] + iv * gv;
                c_reg[u] = cvv;
                float hvv = ov * __tanhf(cvv);
                __stcg(hwrite + (size_t)chainc[u] * HH + jcell[u], hvv);
                __stcg(g_hout + ((size_t)(off + rowc[u]) * TT + t) * (2 * HH) + d * HH + jcell[u], hvv);
            }
        }

        __syncthreads();
        if (tid == 0) {
            red_release_add(bar, 1);
            int target = (s + 1) * 16;
            while (ld_acq(bar) < target) __nanosleep(20);
        }
        __syncthreads();
    }
}

// ---------------- host entry ---------------------------------------------------
extern "C" void kernel_launch(void* const* d_in, const int* in_sizes, int n_in,
                              void* d_out, int out_size) {
    const float* x    = (const float*)d_in[0];
    const float* rW1  = (const float*)d_in[1];
    const float* rb1  = (const float*)d_in[2];
    const float* rW2  = (const float*)d_in[3];
    const float* rb2  = (const float*)d_in[4];
    const float* Wih  = (const float*)d_in[5];
    const float* Whh  = (const float*)d_in[6];
    const float* bih  = (const float*)d_in[7];
    const float* bhh  = (const float*)d_in[8];
    const float* Wout = (const float*)d_in[9];
    const float* bout = (const float*)d_in[10];
    float* out = (float*)d_out;
    (void)in_sizes; (void)n_in;

    cudaFuncSetAttribute(lstm_persist_kernel,
                         cudaFuncAttributeMaxDynamicSharedMemorySize, SMEM_BYTES);
    cudaFuncSetAttribute(xp_gemm_mma_kernel,
                         cudaFuncAttributeMaxDynamicSharedMemorySize, XP_SMEM_BYTES);

    init_mean_r1_kernel<<<96, 512>>>(x, rW1, rb1);                    // 1
    router2_kernel<<<1, 128>>>(rW2, rb2);                             // 2

    dim3 gxp(G4H / 128, TT / 128, NCHAIN);                            // (16, 4, 128)
    xp_gemm_mma_kernel<<<gxp, 256, XP_SMEM_BYTES>>>(x, Wih, bih, bhh);// 3

    lstm_persist_kernel<<<LSTM_BLOCKS, 512, SMEM_BYTES>>>(Whh);       // 4 (profiled)

    dim3 gout(OUTD / TNn, (BB * TT) / TMm);                           // (4, 128)
    out_gemm_fused_kernel<<<gout, 256>>>(Wout, bout, out, out_size);  // 5 (+lb)
}

// round 17
// speedup vs baseline: 1.1505x; 1.1505x over previous
#include <cuda_runtime.h>
#include <cuda_bf16.h>
#include <cstdint>

typedef unsigned long long u64;
typedef unsigned int u32;

// Problem constants
#define BB 32
#define TT 512
#define II 512
#define HH 512
#define G4H 2048
#define EE 4
#define OUTD 512
#define NPAIR 64
#define NCHAIN 128
#define LSTM_BLOCKS 128

// recurrence smem layout (bytes) — R13/R15 layout
#define WF_U64   16384
#define HSTR     516
#define HS_F32   (32 * HSTR)
#define RSTR     17
#define RED_F32  (8 * 32 * RSTR)
#define SMEM_BYTES (WF_U64 * 8 + HS_F32 * 4 + RED_F32 * 4)   // 214,528 B

// mma GEMM smem (xp and out-proj share the layout)
#define XSTR 18
#define XP_SMEM_BYTES (2 * 2 * 128 * XSTR * 4)               // 73,728 B

// ---------------- device scratch ----------------------------------------------
__device__ __align__(16) float g_xp[(size_t)NCHAIN * TT * G4H];       // 512 MB
__device__ __align__(16) float g_hout[(size_t)NPAIR * TT * 2 * HH];   // 128 MB
__device__ __align__(16) float g_hbuf[2][NCHAIN * HH];
__device__ __align__(16) float g_router_h[BB * II];
__device__ int   g_pair_b[NPAIR];
__device__ int   g_pair_e[NPAIR];
__device__ int   g_off[EE];
__device__ int   g_cnt[EE];
__device__ int   g_bpair[BB * 2];
__device__ float g_bw[BB * 2];
__device__ float g_lb;
__device__ int   g_gbar[8];

// ---------------- helpers ------------------------------------------------------
__device__ __forceinline__ u64 ffma2(u64 a, u64 b, u64 c) {
    u64 d;
    asm("fma.rn.f32x2 %0, %1, %2, %3;" : "=l"(d) : "l"(a), "l"(b), "l"(c));
    return d;
}
__device__ __forceinline__ float f2sum(u64 v) {
    float lo, hi;
    asm("mov.b64 {%0,%1}, %2;" : "=f"(lo), "=f"(hi) : "l"(v));
    return lo + hi;
}
__device__ __forceinline__ u64 pack2(float lo, float hi) {
    u64 v;
    asm("mov.b64 %0, {%1,%2};" : "=l"(v) : "f"(lo), "f"(hi));
    return v;
}
__device__ __forceinline__ float sigmoid_fast(float x) {
    return 0.5f * __tanhf(0.5f * x) + 0.5f;
}
__device__ __forceinline__ int ld_acq(const int* p) {
    int v;
    asm volatile("ld.acquire.gpu.b32 %0, [%1];" : "=r"(v) : "l"(p));
    return v;
}
__device__ __forceinline__ void red_release_add(int* p, int v) {
    asm volatile("red.release.gpu.global.add.s32 [%0], %1;" :: "l"(p), "r"(v) : "memory");
}
__device__ __forceinline__ u32 f2tf(float f) {
    u32 r;
    asm("cvt.rna.tf32.f32 %0, %1;" : "=r"(r) : "f"(f));
    return r;
}
__device__ __forceinline__ void mma_tf32(float& d0, float& d1, float& d2, float& d3,
                                         u32 a0, u32 a1, u32 a2, u32 a3,
                                         u32 b0, u32 b1) {
    asm("mma.sync.aligned.m16n8k8.row.col.f32.tf32.tf32.f32 "
        "{%0,%1,%2,%3}, {%4,%5,%6,%7}, {%8,%9}, {%0,%1,%2,%3};"
        : "+f"(d0), "+f"(d1), "+f"(d2), "+f"(d3)
        : "r"(a0), "r"(a1), "r"(a2), "r"(a3), "r"(b0), "r"(b1));
}

// ---- launch 1: fused init + mean + router layer 1 ------------------------------
__global__ __launch_bounds__(512) void init_mean_r1_kernel(
    const float* __restrict__ x, const float* __restrict__ rW1,
    const float* __restrict__ rb1)
{
    int bid = blockIdx.x;
    int tid = threadIdx.x;
    if (bid < BB) {
        __shared__ float rin[II];
        const float* xb = x + (size_t)bid * TT * II + tid;
        float s = 0.f;
        for (int t = 0; t < TT; t++) s += xb[(size_t)t * II];
        rin[tid] = s * (1.0f / (float)TT);
        __syncthreads();
        int n = tid;
        u64 acc2 = 0ull;
        const float* w = rW1 + (size_t)n * II;
        for (int k = 0; k < II; k += 4) {
            float4 wv = *(const float4*)(w + k);
            float4 rv = *(const float4*)&rin[k];
            acc2 = ffma2(pack2(rv.x, rv.y), pack2(wv.x, wv.y), acc2);
            acc2 = ffma2(pack2(rv.z, rv.w), pack2(wv.z, wv.w), acc2);
        }
        float v = f2sum(acc2) + rb1[n];
        float sg = 1.f / (1.f + expf(-v));
        g_router_h[bid * II + n] = v * sg;
    } else {
        int idx = (bid - BB) * 512 + tid;
        g_hbuf[0][idx] = 0.f;
        g_hbuf[0][idx + 32768] = 0.f;
        g_hbuf[1][idx] = 0.f;
        g_hbuf[1][idx + 32768] = 0.f;
        if (bid == BB && tid < 8) g_gbar[tid] = 0;
    }
}

// ---- launch 2: router layer 2 + softmax + top-2 + pair lists -------------------
__global__ __launch_bounds__(128, 1) void router2_kernel(
    const float* __restrict__ rW2, const float* __restrict__ rb2)
{
    __shared__ float logits[BB][EE];
    __shared__ float probs[BB][EE];
    __shared__ float gate[BB][EE];
    int tid = threadIdx.x;
    {
        int b = tid >> 2, e = tid & 3;
        float s = rb2[e];
        const float* w = rW2 + (size_t)e * II;
        const float* h = g_router_h + (size_t)b * II;
        for (int k = 0; k < II; k++) s += h[k] * w[k];
        logits[b][e] = s;
    }
    __syncthreads();
    if (tid < BB) {
        int b = tid;
        float m = logits[b][0];
        for (int e = 1; e < EE; e++) m = fmaxf(m, logits[b][e]);
        float pr[EE], sum = 0.f;
        for (int e = 0; e < EE; e++) { pr[e] = expf(logits[b][e] - m); sum += pr[e]; }
        for (int e = 0; e < EE; e++) { pr[e] /= sum; probs[b][e] = pr[e]; gate[b][e] = 0.f; }
        int i1 = 0;
        for (int e = 1; e < EE; e++) if (pr[e] > pr[i1]) i1 = e;
        int i2 = -1;
        for (int e = 0; e < EE; e++) {
            if (e == i1) continue;
            if (i2 < 0 || pr[e] > pr[i2]) i2 = e;
        }
        float ws = pr[i1] + pr[i2];
        gate[b][i1] = pr[i1] / ws;
        gate[b][i2] = pr[i2] / ws;
    }
    __syncthreads();
    if (tid == 0) {
        float lb = 0.f;
        for (int e = 0; e < EE; e++) {
            float u = 0.f;
            for (int b = 0; b < BB; b++) u += probs[b][e];
            u *= (1.f / (float)BB);
            float d = u - 1.0f / (float)EE;
            lb += d * d;
        }
        g_lb = 0.01f * (lb / (float)EE);
        int P = 0;
        int slotc[BB];
        for (int b = 0; b < BB; b++) slotc[b] = 0;
        for (int e = 0; e < EE; e++) {
            g_off[e] = P;
            for (int b = 0; b < BB; b++) {
                if (gate[b][e] > 0.f) {
                    g_pair_b[P] = b;
                    g_pair_e[P] = e;
                    g_bpair[b * 2 + slotc[b]] = P;
                    g_bw[b * 2 + slotc[b]] = gate[b][e];
                    slotc[b]++;
                    P++;
                }
            }
            g_cnt[e] = P - g_off[e];
        }
    }
}

// ---------------- xp GEMM on tensor pipe (tf32 m16n8k8) — R15 version ----------
__global__ __launch_bounds__(256, 2) void xp_gemm_mma_kernel(
    const float* __restrict__ x, const float* __restrict__ Wih,
    const float* __restrict__ bih, const float* __restrict__ bhh)
{
    extern __shared__ u32 xsm[];
    u32* As = xsm;
    u32* Bs = xsm + 2 * 128 * XSTR;

    int z = blockIdx.z;
    int p = z >> 1, d = z & 1;
    int b = g_pair_b[p];
    int e = g_pair_e[p];
    int ed = e * 2 + d;
    const float* A  = x + (size_t)b * TT * II;
    const float* Bw = Wih + (size_t)ed * G4H * II;
    const float* b1 = bih + (size_t)ed * G4H;
    const float* b2 = bhh + (size_t)ed * G4H;
    float* C = g_xp + (size_t)z * TT * G4H;
    int m0 = blockIdx.y * 128, n0 = blockIdx.x * 128;

    int tid = threadIdx.x;
    int w = tid >> 5, lane = tid & 31;
    int wm = w >> 2, wn = w & 3;
    int lg = lane >> 2, lt = lane & 3;

    float acc[4][4][4];
#pragma unroll
    for (int mt = 0; mt < 4; mt++)
#pragma unroll
        for (int nt = 0; nt < 4; nt++)
#pragma unroll
            for (int q = 0; q < 4; q++) acc[mt][nt][q] = 0.f;

    int srow[2], skv[2], spb[2];
#pragma unroll
    for (int it = 0; it < 2; it++) {
        int idx = tid + it * 256;
        srow[it] = idx >> 2;
        skv[it] = (idx & 3) * 4;
        spb[it] = 8 * (skv[it] >> 3) + ((skv[it] >> 2) & 1);
    }

    float4 pa[2], pbv[2];
#pragma unroll
    for (int it = 0; it < 2; it++) {
        pa[it]  = *(const float4*)(A  + (size_t)(m0 + srow[it]) * II + skv[it]);
        pbv[it] = *(const float4*)(Bw + (size_t)(n0 + srow[it]) * II + skv[it]);
    }

    for (int kt = 0; kt < 32; kt++) {
        int bsel = kt & 1;
        u32* Ab = As + bsel * (128 * XSTR);
        u32* Bb = Bs + bsel * (128 * XSTR);
#pragma unroll
        for (int it = 0; it < 2; it++) {
            int abase = srow[it] * XSTR + spb[it];
            Ab[abase + 0] = f2tf(pa[it].x);
            Ab[abase + 2] = f2tf(pa[it].y);
            Ab[abase + 4] = f2tf(pa[it].z);
            Ab[abase + 6] = f2tf(pa[it].w);
            Bb[abase + 0] = f2tf(pbv[it].x);
            Bb[abase + 2] = f2tf(pbv[it].y);
            Bb[abase + 4] = f2tf(pbv[it].z);
            Bb[abase + 6] = f2tf(pbv[it].w);
        }
        __syncthreads();
        if (kt < 31) {
            int k0n = (kt + 1) * 16;
#pragma unroll
            for (int it = 0; it < 2; it++) {
                pa[it]  = *(const float4*)(A  + (size_t)(m0 + srow[it]) * II + k0n + skv[it]);
                pbv[it] = *(const float4*)(Bw + (size_t)(n0 + srow[it]) * II + k0n + skv[it]);
            }
        }
#pragma unroll
        for (int h = 0; h < 2; h++) {
            u32 a0[4], a1[4], a2[4], a3[4];
#pragma unroll
            for (int mt = 0; mt < 4; mt++) {
                int r = wm * 64 + mt * 16 + lg;
                u64 v  = *(const u64*)&Ab[r * XSTR + h * 8 + 2 * lt];
                u64 v2 = *(const u64*)&Ab[(r + 8) * XSTR + h * 8 + 2 * lt];
                a0[mt] = (u32)v;  a2[mt] = (u32)(v >> 32);
                a1[mt] = (u32)v2; a3[mt] = (u32)(v2 >> 32);
            }
            u32 bf0[4], bf1[4];
#pragma unroll
            for (int nt = 0; nt < 4; nt++) {
                int rn = wn * 32 + nt * 8 + lg;
                u64 v = *(const u64*)&Bb[rn * XSTR + h * 8 + 2 * lt];
                bf0[nt] = (u32)v; bf1[nt] = (u32)(v >> 32);
            }
#pragma unroll
            for (int mt = 0; mt < 4; mt++)
#pragma unroll
                for (int nt = 0; nt < 4; nt++)
                    mma_tf32(acc[mt][nt][0], acc[mt][nt][1], acc[mt][nt][2], acc[mt][nt][3],
                             a0[mt], a1[mt], a2[mt], a3[mt], bf0[nt], bf1[nt]);
        }
    }

#pragma unroll
    for (int mt = 0; mt < 4; mt++) {
        int r0 = m0 + wm * 64 + mt * 16 + lg;
#pragma unroll
        for (int nt = 0; nt < 4; nt++) {
            int c = n0 + wn * 32 + nt * 8 + 2 * lt;
            float bv0 = b1[c] + b2[c];
            float bv1 = b1[c + 1] + b2[c + 1];
            *(float2*)&C[(size_t)r0 * G4H + c] =
                make_float2(acc[mt][nt][0] + bv0, acc[mt][nt][1] + bv1);
            *(float2*)&C[(size_t)(r0 + 8) * G4H + c] =
                make_float2(acc[mt][nt][2] + bv0, acc[mt][nt][3] + bv1);
        }
    }
}

// ---------- out-proj on tensor pipe (tf32 mma) with fused gate-combine ---------
// out[M=16384, N=512] = (w0*hout[p0] + w1*hout[p1]) @ Wout^T + bout; K=1024.
__global__ __launch_bounds__(256, 2) void out_gemm_mma_kernel(
    const float* __restrict__ Wout, const float* __restrict__ bout,
    float* __restrict__ out, int out_size)
{
    extern __shared__ u32 xsm[];
    u32* As = xsm;
    u32* Bs = xsm + 2 * 128 * XSTR;
    const int K = 2 * HH;

    int m0 = blockIdx.y * 128, n0 = blockIdx.x * 128;
    int tid = threadIdx.x;
    int w = tid >> 5, lane = tid & 31;
    int wm = w >> 2, wn = w & 3;
    int lg = lane >> 2, lt = lane & 3;

    float acc[4][4][4];
#pragma unroll
    for (int mt = 0; mt < 4; mt++)
#pragma unroll
        for (int nt = 0; nt < 4; nt++)
#pragma unroll
            for (int q = 0; q < 4; q++) acc[mt][nt][q] = 0.f;

    int srow[2], skv[2], spb[2];
    const float* hsrc0[2];
    const float* hsrc1[2];
    float aw0[2], aw1[2];
#pragma unroll
    for (int it = 0; it < 2; it++) {
        int idx = tid + it * 256;
        srow[it] = idx >> 2;
        skv[it] = (idx & 3) * 4;
        spb[it] = 8 * (skv[it] >> 3) + ((skv[it] >> 2) & 1);
        int m = m0 + srow[it];
        int b = m >> 9, t = m & (TT - 1);
        int p0 = g_bpair[b * 2 + 0], p1 = g_bpair[b * 2 + 1];
        aw0[it] = g_bw[b * 2 + 0];
        aw1[it] = g_bw[b * 2 + 1];
        hsrc0[it] = g_hout + ((size_t)p0 * TT + t) * (2 * HH) + skv[it];
        hsrc1[it] = g_hout + ((size_t)p1 * TT + t) * (2 * HH) + skv[it];
    }

    float4 pa[2], pbv[2];
#pragma unroll
    for (int it = 0; it < 2; it++) {
        float4 v0 = __ldg((const float4*)hsrc0[it]);
        float4 v1 = __ldg((const float4*)hsrc1[it]);
        pa[it] = make_float4(aw0[it] * v0.x + aw1[it] * v1.x, aw0[it] * v0.y + aw1[it] * v1.y,
                             aw0[it] * v0.z + aw1[it] * v1.z, aw0[it] * v0.w + aw1[it] * v1.w);
        pbv[it] = *(const float4*)(Wout + (size_t)(n0 + srow[it]) * K + skv[it]);
    }

    int nk = K / 16;          // 64
    for (int kt = 0; kt < nk; kt++) {
        int bsel = kt & 1;
        u32* Ab = As + bsel * (128 * XSTR);
        u32* Bb = Bs + bsel * (128 * XSTR);
#pragma unroll
        for (int it = 0; it < 2; it++) {
            int abase = srow[it] * XSTR + spb[it];
            Ab[abase + 0] = f2tf(pa[it].x);
            Ab[abase + 2] = f2tf(pa[it].y);
            Ab[abase + 4] = f2tf(pa[it].z);
            Ab[abase + 6] = f2tf(pa[it].w);
            Bb[abase + 0] = f2tf(pbv[it].x);
            Bb[abase + 2] = f2tf(pbv[it].y);
            Bb[abase + 4] = f2tf(pbv[it].z);
            Bb[abase + 6] = f2tf(pbv[it].w);
        }
        __syncthreads();
        if (kt + 1 < nk) {
            int k0n = (kt + 1) * 16;
#pragma unroll
            for (int it = 0; it < 2; it++) {
                float4 v0 = __ldg((const float4*)(hsrc0[it] + k0n));
                float4 v1 = __ldg((const float4*)(hsrc1[it] + k0n));
                pa[it] = make_float4(aw0[it] * v0.x + aw1[it] * v1.x, aw0[it] * v0.y + aw1[it] * v1.y,
                                     aw0[it] * v0.z + aw1[it] * v1.z, aw0[it] * v0.w + aw1[it] * v1.w);
                pbv[it] = *(const float4*)(Wout + (size_t)(n0 + srow[it]) * K + k0n + skv[it]);
            }
        }
#pragma unroll
        for (int h = 0; h < 2; h++) {
            u32 a0[4], a1[4], a2[4], a3[4];
#pragma unroll
            for (int mt = 0; mt < 4; mt++) {
                int r = wm * 64 + mt * 16 + lg;
                u64 v  = *(const u64*)&Ab[r * XSTR + h * 8 + 2 * lt];
                u64 v2 = *(const u64*)&Ab[(r + 8) * XSTR + h * 8 + 2 * lt];
                a0[mt] = (u32)v;  a2[mt] = (u32)(v >> 32);
                a1[mt] = (u32)v2; a3[mt] = (u32)(v2 >> 32);
            }
            u32 bf0[4], bf1[4];
#pragma unroll
            for (int nt = 0; nt < 4; nt++) {
                int rn = wn * 32 + nt * 8 + lg;
                u64 v = *(const u64*)&Bb[rn * XSTR + h * 8 + 2 * lt];
                bf0[nt] = (u32)v; bf1[nt] = (u32)(v >> 32);
            }
#pragma unroll
            for (int mt = 0; mt < 4; mt++)
#pragma unroll
                for (int nt = 0; nt < 4; nt++)
                    mma_tf32(acc[mt][nt][0], acc[mt][nt][1], acc[mt][nt][2], acc[mt][nt][3],
                             a0[mt], a1[mt], a2[mt], a3[mt], bf0[nt], bf1[nt]);
        }
    }

#pragma unroll
    for (int mt = 0; mt < 4; mt++) {
        int r0 = m0 + wm * 64 + mt * 16 + lg;
#pragma unroll
        for (int nt = 0; nt < 4; nt++) {
            int c = n0 + wn * 32 + nt * 8 + 2 * lt;
            float bv0 = bout[c];
            float bv1 = bout[c + 1];
            *(float2*)&out[(size_t)r0 * OUTD + c] =
                make_float2(acc[mt][nt][0] + bv0, acc[mt][nt][1] + bv1);
            *(float2*)&out[(size_t)(r0 + 8) * OUTD + c] =
                make_float2(acc[mt][nt][2] + bv0, acc[mt][nt][3] + bv1);
        }
    }
    if (blockIdx.x == 0 && blockIdx.y == 0 && tid == 0)
        out[out_size - 1] = g_lb;
}

// ---- persistent LSTM recurrence: tf32 mma, k-split + nt-skip (R15) ------------
__global__ __launch_bounds__(512, 1) void lstm_persist_kernel(const float* __restrict__ Whh) {
    extern __shared__ __align__(16) char smem_dyn[];
    u64* wfrag = (u64*)smem_dyn;
    u32* hs    = (u32*)(smem_dyn + WF_U64 * 8);
    float* red = (float*)(smem_dyn + WF_U64 * 8 + HS_F32 * 4);

    int bid = blockIdx.x;
    int g = bid >> 4;
    int ct = bid & 15;
    int e = g >> 1, d = g & 1;
    int cnt = g_cnt[e];
    int off = g_off[e];
    int j0 = ct * 32;
    if (cnt == 0) return;

    int tid = threadIdx.x;
    int w = tid >> 5, lane = tid & 31;
    int kh = w & 1, og = w >> 1;

    const float* W = Whh + (size_t)g * G4H * HH;

    for (int it = 0; it < 32; it++) {
        int id = tid + it * 512;
        int ln = id & 31;
        int kt = (id >> 5) & 63;
        int ogp = id >> 11;
        int gatep = ogp & 3, chp = ogp >> 2;
        int m0 = ln >> 2;
        int k = kt * 8 + (ln & 3);
        int ra = gatep * HH + j0 + chp * 16 + m0;
        float w00 = W[(size_t)ra * HH + k];
        float w10 = W[(size_t)(ra + 8) * HH + k];
        float w01 = W[(size_t)ra * HH + k + 4];
        float w11 = W[(size_t)(ra + 8) * HH + k + 4];
        u32 lo = ((u32)__bfloat16_as_ushort(__float2bfloat16_rn(w00))) |
                 (((u32)__bfloat16_as_ushort(__float2bfloat16_rn(w10))) << 16);
        u32 hi = ((u32)__bfloat16_as_ushort(__float2bfloat16_rn(w01))) |
                 (((u32)__bfloat16_as_ushort(__float2bfloat16_rn(w11))) << 16);
        wfrag[id] = ((u64)hi << 32) | lo;
    }

    int colc[2], rowc[2], chainc[2], lslot[2], iidx[2], ogb[2];
    float c_reg[2];
#pragma unroll
    for (int u = 0; u < 2; u++) {
        int cid = tid * 2 + u;
        colc[u] = cid >> 5;
        rowc[u] = cid & 31;
        chainc[u] = (off + rowc[u]) * 2 + d;
        int m = colc[u] & 15;
        int nt = rowc[u] >> 3;
        lslot[u] = (m & 7) * 4 + ((rowc[u] & 7) >> 1);
        iidx[u] = nt * 4 + (m >> 3) * 2 + (rowc[u] & 1);
        ogb[u] = (colc[u] >> 4) << 2;
        c_reg[u] = 0.f;
    }
    int jcell[2] = { j0 + colc[0], j0 + colc[1] };

    int* bar = &g_gbar[g];
    const u64* wfw = wfrag + (size_t)og * 2048 + (size_t)kh * 32 * 32;

    __syncthreads();

    for (int s = 0; s < TT; s++) {
        int rb = s & 1;
        int t = d ? (TT - 1 - s) : s;
        const float* hread = g_hbuf[rb];
        float* hwrite = g_hbuf[rb ^ 1];

        float xq[2][4];
#pragma unroll
        for (int u = 0; u < 2; u++) {
            xq[u][0] = xq[u][1] = xq[u][2] = xq[u][3] = 0.f;
            if (rowc[u] < cnt) {
                const float* xpt = g_xp + ((size_t)chainc[u] * TT + t) * G4H;
#pragma unroll
                for (int gg = 0; gg < 4; gg++)
                    xq[u][gg] = __ldg(xpt + gg * HH + jcell[u]);
            }
        }

#pragma unroll
        for (int it = 0; it < 8; it++) {
            int idx = tid + it * 512;
            int row = idx >> 7;
            int f4 = idx & 127;
            float4 v = make_float4(0.f, 0.f, 0.f, 0.f);
            if (row < cnt)
                v = __ldcg((const float4*)(hread + (size_t)((off + row) * 2 + d) * HH + f4 * 4));
            uint4 tv;
            tv.x = f2tf(v.x); tv.y = f2tf(v.y); tv.z = f2tf(v.z); tv.w = f2tf(v.w);
            *(uint4*)&hs[row * HSTR + f4 * 4] = tv;
        }
        __syncthreads();

        float acc[16];
#pragma unroll
        for (int i = 0; i < 16; i++) acc[i] = 0.f;

        int kb = kh * 256;
        int brow = lane >> 2;
        int bk = lane & 3;
#pragma unroll 8
        for (int ktl = 0; ktl < 32; ktl++) {
            u64 wv = wfw[ktl * 32 + lane];
            u32 lo = (u32)wv, hi = (u32)(wv >> 32);
            u32 a0 = lo << 16;
            u32 a1 = lo & 0xFFFF0000u;
            u32 a2 = hi << 16;
            u32 a3 = hi & 0xFFFF0000u;
            int k0 = kb + ktl * 8;
#pragma unroll
            for (int nt = 0; nt < 4; nt++) {
                if (nt * 8 < cnt) {
                    u32 b0 = hs[(nt * 8 + brow) * HSTR + k0 + bk];
                    u32 b1 = hs[(nt * 8 + brow) * HSTR + k0 + bk + 4];
                    mma_tf32(acc[nt * 4 + 0], acc[nt * 4 + 1], acc[nt * 4 + 2], acc[nt * 4 + 3],
                             a0, a1, a2, a3, b0, b1);
                }
            }
        }

        if (kh == 1) {
            float* rp = red + (og * 32 + lane) * RSTR;
#pragma unroll
            for (int i = 0; i < 16; i++) rp[i] = acc[i];
        }
        __syncthreads();
        if (kh == 0) {
            float* rp = red + (og * 32 + lane) * RSTR;
#pragma unroll
            for (int i = 0; i < 16; i++) acc[i] += rp[i];
#pragma unroll
            for (int i = 0; i < 16; i++) rp[i] = acc[i];
        }
        __syncthreads();

#pragma unroll
        for (int u = 0; u < 2; u++) {
            if (rowc[u] < cnt) {
                float gi = xq[u][0] + red[((ogb[u] + 0) * 32 + lslot[u]) * RSTR + iidx[u]];
                float gf = xq[u][1] + red[((ogb[u] + 1) * 32 + lslot[u]) * RSTR + iidx[u]];
                float gg = xq[u][2] + red[((ogb[u] + 2) * 32 + lslot[u]) * RSTR + iidx[u]];
                float go = xq[u][3] + red[((ogb[u] + 3) * 32 + lslot[u]) * RSTR + iidx[u]];
                float iv = sigmoid_fast(gi);
                float fv = sigmoid_fast(gf);
                float gv = __tanhf(gg);
                float ov = sigmoid_fast(go);
                float cvv = fv * c_reg[u] + iv * gv;
                c_reg[u] = cvv;
                float hvv = ov * __tanhf(cvv);
                __stcg(hwrite + (size_t)chainc[u] * HH + jcell[u], hvv);
                __stcg(g_hout + ((size_t)(off + rowc[u]) * TT + t) * (2 * HH) + d * HH + jcell[u], hvv);
            }
        }

        __syncthreads();
        if (tid == 0) {
            red_release_add(bar, 1);
            int target = (s + 1) * 16;
            while (ld_acq(bar) < target) __nanosleep(20);
        }
        __syncthreads();
    }
}

// ---------------- host entry ---------------------------------------------------
extern "C" void kernel_launch(void* const* d_in, const int* in_sizes, int n_in,
                              void* d_out, int out_size) {
    const float* x    = (const float*)d_in[0];
    const float* rW1  = (const float*)d_in[1];
    const float* rb1  = (const float*)d_in[2];
    const float* rW2  = (const float*)d_in[3];
    const float* rb2  = (const float*)d_in[4];
    const float* Wih  = (const float*)d_in[5];
    const float* Whh  = (const float*)d_in[6];
    const float* bih  = (const float*)d_in[7];
    const float* bhh  = (const float*)d_in[8];
    const float* Wout = (const float*)d_in[9];
    const float* bout = (const float*)d_in[10];
    float* out = (float*)d_out;
    (void)in_sizes; (void)n_in;

    cudaFuncSetAttribute(lstm_persist_kernel,
                         cudaFuncAttributeMaxDynamicSharedMemorySize, SMEM_BYTES);
    cudaFuncSetAttribute(xp_gemm_mma_kernel,
                         cudaFuncAttributeMaxDynamicSharedMemorySize, XP_SMEM_BYTES);
    cudaFuncSetAttribute(out_gemm_mma_kernel,
                         cudaFuncAttributeMaxDynamicSharedMemorySize, XP_SMEM_BYTES);

    init_mean_r1_kernel<<<96, 512>>>(x, rW1, rb1);                    // 1
    router2_kernel<<<1, 128>>>(rW2, rb2);                             // 2

    dim3 gxp(G4H / 128, TT / 128, NCHAIN);                            // (16, 4, 128)
    xp_gemm_mma_kernel<<<gxp, 256, XP_SMEM_BYTES>>>(x, Wih, bih, bhh);// 3

    lstm_persist_kernel<<<LSTM_BLOCKS, 512, SMEM_BYTES>>>(Whh);       // 4 (profiled)

    dim3 gout(OUTD / 128, (BB * TT) / 128);                           // (4, 128)
    out_gemm_mma_kernel<<<gout, 256, XP_SMEM_BYTES>>>(Wout, bout, out, out_size); // 5
}